// round 1
// baseline (speedup 1.0000x reference)
#include <cuda_runtime.h>
#include <math.h>

// Problem constants
#define BSZ   16384
#define INSZ  512
#define OUTSZ 512
#define ORD   10
#define KTOT  (INSZ * (ORD + 1))   // 5632 = 512 (silu) + 10*512 (cheby, scrambled)

// Scratch: device globals (no cudaMalloc allowed).
// Act: 16384 x 5632 fp32 = 352 MB; Wc: 512 x 5632 fp32 = 11 MB.
__device__ float g_act[(size_t)BSZ * KTOT];
__device__ float g_wc[(size_t)OUTSZ * KTOT];

// ---------------------------------------------------------------------------
// Build combined weight: Wc[out, 0:512] = base_weight[out,:]
//                        Wc[out, 512+j] = 0.1 * cheby_weight.flat[out*5120 + j]
// (the reference's w reshape is contiguous, so the spline part is a scaled copy)
// ---------------------------------------------------------------------------
__global__ void build_wc_kernel(const float* __restrict__ base_w,
                                const float* __restrict__ cheby_w) {
    int idx = blockIdx.x * blockDim.x + threadIdx.x;   // exactly 512*5632 threads
    int out = idx / KTOT;
    int k   = idx - out * KTOT;
    float v;
    if (k < INSZ) v = base_w[out * INSZ + k];
    else          v = 0.1f * cheby_w[out * (INSZ * ORD) + (k - INSZ)];
    g_wc[idx] = v;
}

// ---------------------------------------------------------------------------
// Build activation matrix with the reference's scrambled view semantics:
//   Act[b, i]                 = silu(x[b, i])
//   Act[b, 512 + o'*512 + i]  = T_o(x[bb, i]),  m = 10b + o', o = m>>14, bb = m&16383
// Iterate over (o, bb) instead: m = o*16384 + bb, b = m/10, o' = m%10  (bijection)
// -> each write is a coalesced, contiguous 512-float row segment.
// One block per bb row (512 threads), chebyshev recurrence kept in registers.
// ---------------------------------------------------------------------------
__global__ void build_act_kernel(const float* __restrict__ x) {
    int bb = blockIdx.x;
    int i  = threadIdx.x;                       // 0..511
    float xv = x[bb * INSZ + i];

    // silu path
    float s = xv / (1.0f + expf(-xv));
    g_act[(size_t)bb * KTOT + i] = s;

    // chebyshev T_0..T_9 with scatter by order
    float tm2 = 1.0f;   // T_{o-2}
    float tm1 = xv;     // T_{o-1}
    #pragma unroll
    for (int o = 0; o < ORD; o++) {
        float t;
        if (o == 0)      t = 1.0f;
        else if (o == 1) t = xv;
        else { t = 2.0f * xv * tm1 - tm2; tm2 = tm1; tm1 = t; }
        int m  = o * BSZ + bb;
        int b  = m / 10;
        int op = m - b * 10;
        g_act[(size_t)b * KTOT + INSZ + op * INSZ + i] = t;
    }
}

// ---------------------------------------------------------------------------
// fp32 SIMT GEMM: C[M,N] = Act[M,K] @ Wc[N,K]^T,  M=16384 N=512 K=5632
// 128x128 tile, BK=16, 256 threads, 8x8 per thread, double-buffered SMEM.
// ---------------------------------------------------------------------------
#define BM 128
#define BN 128
#define BK 16
#define PAD 132   // 128 + 4 to break 4-way bank conflicts on transposed stores

__global__ __launch_bounds__(256, 2) void gemm_kernel(float* __restrict__ C) {
    __shared__ float As[2][BK][PAD];
    __shared__ float Bs[2][BK][PAD];
    const int K = KTOT;

    int tid = threadIdx.x;
    int lr = tid >> 2;            // 0..63 (loads rows lr and lr+64)
    int lc = (tid & 3) << 2;      // 0,4,8,12 (k offset within the BK=16 slab)

    const float* aptr = g_act + (size_t)(blockIdx.y * BM + lr) * K + lc;
    const float* bptr = g_wc  + (size_t)(blockIdx.x * BN + lr) * K + lc;

    const int ty4 = (tid >> 4) << 2;  // row-fragment base (0..60)
    const int tx4 = (tid & 15) << 2;  // col-fragment base (0..60)

    float acc[8][8];
    #pragma unroll
    for (int ii = 0; ii < 8; ii++)
        #pragma unroll
        for (int jj = 0; jj < 8; jj++) acc[ii][jj] = 0.0f;

    float4 ra0, ra1, rb0, rb1;

    // prologue: tile 0 -> buffer 0
    ra0 = *(const float4*)(aptr);
    ra1 = *(const float4*)(aptr + (size_t)64 * K);
    rb0 = *(const float4*)(bptr);
    rb1 = *(const float4*)(bptr + (size_t)64 * K);
    As[0][lc + 0][lr]      = ra0.x; As[0][lc + 1][lr]      = ra0.y;
    As[0][lc + 2][lr]      = ra0.z; As[0][lc + 3][lr]      = ra0.w;
    As[0][lc + 0][lr + 64] = ra1.x; As[0][lc + 1][lr + 64] = ra1.y;
    As[0][lc + 2][lr + 64] = ra1.z; As[0][lc + 3][lr + 64] = ra1.w;
    Bs[0][lc + 0][lr]      = rb0.x; Bs[0][lc + 1][lr]      = rb0.y;
    Bs[0][lc + 2][lr]      = rb0.z; Bs[0][lc + 3][lr]      = rb0.w;
    Bs[0][lc + 0][lr + 64] = rb1.x; Bs[0][lc + 1][lr + 64] = rb1.y;
    Bs[0][lc + 2][lr + 64] = rb1.z; Bs[0][lc + 3][lr + 64] = rb1.w;
    __syncthreads();

    const int NK = K / BK;   // 352
    for (int kt = 0; kt < NK; kt++) {
        int cur = kt & 1;
        int nxt = cur ^ 1;

        // prefetch next tile into registers (hides LDG under the FMA block)
        if (kt + 1 < NK) {
            const float* ap = aptr + (size_t)(kt + 1) * BK;
            const float* bp = bptr + (size_t)(kt + 1) * BK;
            ra0 = *(const float4*)(ap);
            ra1 = *(const float4*)(ap + (size_t)64 * K);
            rb0 = *(const float4*)(bp);
            rb1 = *(const float4*)(bp + (size_t)64 * K);
        }

        #pragma unroll
        for (int k = 0; k < BK; k++) {
            float4 a0 = *(const float4*)&As[cur][k][ty4];
            float4 a1 = *(const float4*)&As[cur][k][ty4 + 64];
            float4 b0 = *(const float4*)&Bs[cur][k][tx4];
            float4 b1 = *(const float4*)&Bs[cur][k][tx4 + 64];
            float a[8] = {a0.x, a0.y, a0.z, a0.w, a1.x, a1.y, a1.z, a1.w};
            float b[8] = {b0.x, b0.y, b0.z, b0.w, b1.x, b1.y, b1.z, b1.w};
            #pragma unroll
            for (int ii = 0; ii < 8; ii++)
                #pragma unroll
                for (int jj = 0; jj < 8; jj++)
                    acc[ii][jj] = fmaf(a[ii], b[jj], acc[ii][jj]);
        }

        if (kt + 1 < NK) {
            As[nxt][lc + 0][lr]      = ra0.x; As[nxt][lc + 1][lr]      = ra0.y;
            As[nxt][lc + 2][lr]      = ra0.z; As[nxt][lc + 3][lr]      = ra0.w;
            As[nxt][lc + 0][lr + 64] = ra1.x; As[nxt][lc + 1][lr + 64] = ra1.y;
            As[nxt][lc + 2][lr + 64] = ra1.z; As[nxt][lc + 3][lr + 64] = ra1.w;
            Bs[nxt][lc + 0][lr]      = rb0.x; Bs[nxt][lc + 1][lr]      = rb0.y;
            Bs[nxt][lc + 2][lr]      = rb0.z; Bs[nxt][lc + 3][lr]      = rb0.w;
            Bs[nxt][lc + 0][lr + 64] = rb1.x; Bs[nxt][lc + 1][lr + 64] = rb1.y;
            Bs[nxt][lc + 2][lr + 64] = rb1.z; Bs[nxt][lc + 3][lr + 64] = rb1.w;
        }
        __syncthreads();
    }

    // epilogue: 8x8 per thread as 2x2 blocks of 4x4, float4 stores
    int row0 = blockIdx.y * BM + ty4;
    int col0 = blockIdx.x * BN + tx4;
    #pragma unroll
    for (int ih = 0; ih < 2; ih++) {
        #pragma unroll
        for (int ii = 0; ii < 4; ii++) {
            int r = row0 + ih * 64 + ii;
            #pragma unroll
            for (int jh = 0; jh < 2; jh++) {
                float4 v;
                v.x = acc[ih * 4 + ii][jh * 4 + 0];
                v.y = acc[ih * 4 + ii][jh * 4 + 1];
                v.z = acc[ih * 4 + ii][jh * 4 + 2];
                v.w = acc[ih * 4 + ii][jh * 4 + 3];
                *(float4*)&C[(size_t)r * OUTSZ + col0 + jh * 64] = v;
            }
        }
    }
}

// ---------------------------------------------------------------------------
// Launch
// ---------------------------------------------------------------------------
extern "C" void kernel_launch(void* const* d_in, const int* in_sizes, int n_in,
                              void* d_out, int out_size) {
    const float* x  = (const float*)d_in[0];   // (16384, 512)
    const float* bw = (const float*)d_in[1];   // (512, 512)
    const float* cw = (const float*)d_in[2];   // (512, 512, 10)
    float* out = (float*)d_out;                // (16384, 512) fp32

    build_wc_kernel<<<(OUTSZ * KTOT) / 256, 256>>>(bw, cw);
    build_act_kernel<<<BSZ, INSZ>>>(x);

    dim3 grid(OUTSZ / BN, BSZ / BM);  // (4, 128)
    gemm_kernel<<<grid, 256>>>(out);
}

// round 5
// speedup vs baseline: 4.7671x; 4.7671x over previous
#include <cuda_runtime.h>
#include <cuda_fp16.h>
#include <math.h>
#include <stdint.h>

// ---------------------------------------------------------------- constants
#define BSZ   16384
#define INSZ  512
#define OUTSZ 512
#define ORD   10
#define KTOT  5632              // 512 silu + 10*512 scrambled chebyshev
#define BM    128
#define BN    128
#define BK    64
#define NKT   (KTOT / BK)       // 88
#define STAGES 3
#define STAGE_BYTES 32768       // A 16KB + B 16KB
#define SMEM_BYTES  (STAGES * STAGE_BYTES)   // 98304

// ---------------------------------------------------------------- scratch
__device__ __align__(16) __half g_a[(size_t)BSZ * KTOT];   // 176 MB
__device__ __align__(16) __half g_b[(size_t)OUTSZ * KTOT]; // 5.6 MB

// --------------------------------------------------------------- builders
// Wc[out, 0:512] = base_weight ; Wc[out, 512+j] = 0.1 * cheby.flat[out*5120+j]
__global__ void build_wc_kernel(const float* __restrict__ base_w,
                                const float* __restrict__ cheby_w) {
    int idx = blockIdx.x * blockDim.x + threadIdx.x;  // 512*5632 threads
    int out = idx / KTOT;
    int k   = idx - out * KTOT;
    float v = (k < INSZ) ? base_w[out * INSZ + k]
                         : 0.1f * cheby_w[out * (INSZ * ORD) + (k - INSZ)];
    g_b[idx] = __float2half_rn(v);
}

// Act[b,i]=silu(x[b,i]); Act[b,512+o'*512+i]=T_o(x[bb,i]) with m=10b+o', o=m>>14,
// bb=m&16383. Iterate (o,bb): m=o*16384+bb, b=m/10, o'=m%10 (coalesced writes).
__global__ void build_act_kernel(const float* __restrict__ x) {
    int bb = blockIdx.x;
    int i  = threadIdx.x;
    float xv = x[bb * INSZ + i];

    float s = xv / (1.0f + expf(-xv));
    g_a[(size_t)bb * KTOT + i] = __float2half_rn(s);

    float tm2 = 1.0f, tm1 = xv;
    #pragma unroll
    for (int o = 0; o < ORD; o++) {
        float t;
        if (o == 0)      t = 1.0f;
        else if (o == 1) t = xv;
        else { t = 2.0f * xv * tm1 - tm2; tm2 = tm1; tm1 = t; }
        int m  = o * BSZ + bb;
        int b  = m / 10;
        int op = m - b * 10;
        g_a[(size_t)b * KTOT + INSZ + op * INSZ + i] = __float2half_rn(t);
    }
}

// --------------------------------------------------------- PTX primitives
__device__ __forceinline__ uint32_t smem_u32(const void* p) {
    uint32_t a;
    asm("{ .reg .u64 t; cvta.to.shared.u64 t, %1; cvt.u32.u64 %0, t; }" : "=r"(a) : "l"(p));
    return a;
}
__device__ __forceinline__ void cp16(uint32_t dst, const void* src) {
    asm volatile("cp.async.cg.shared.global [%0], [%1], 16;" :: "r"(dst), "l"(src));
}

// ------------------------------------------------------------- HMMA GEMM
// C[16384, 512] = A[16384, 5632] @ B[512, 5632]^T, fp16 in, fp32 accum.
// CTA tile 128x128, BK=64, 3-stage cp.async pipeline, 8 warps (2m x 4n),
// warp tile 64x32 via mma.sync m16n8k16, ldmatrix fragment loads.
// SMEM tiles: [row][64 fp16] = 128B rows; 16B chunk c swizzled c^(row&7).
__global__ void __launch_bounds__(256, 2) gemm_hmma_kernel(float* __restrict__ out) {
    extern __shared__ char smem[];
    uint32_t su = smem_u32(smem);
    int tid = threadIdx.x, lane = tid & 31, wid = tid >> 5;
    int mOff = (wid & 1) * 64;
    int nOff = (wid >> 1) * 32;
    int rowBase = blockIdx.y * BM;
    int colBase = blockIdx.x * BN;

    const __half* Ag = g_a + (size_t)rowBase * KTOT;
    const __half* Bg = g_b + (size_t)colBase * KTOT;

    // loader: 128 rows x 8 chunks(16B); 2 threads/row, 4 chunks each
    int lr  = tid >> 1;          // 0..127
    int lc4 = (tid & 1) * 4;     // chunk base 0 or 4

    float acc[4][4][4];
    #pragma unroll
    for (int mi = 0; mi < 4; mi++)
        #pragma unroll
        for (int ni = 0; ni < 4; ni++)
            #pragma unroll
            for (int q = 0; q < 4; q++) acc[mi][ni][q] = 0.0f;

    // ldmatrix lane address components (canonical m16n8k16 mapping)
    int a_r = lane & 15, a_k = lane >> 4;        // A: x4
    int b_r = lane & 7,  b_k = (lane >> 3) & 1;  // B: x2 (lanes 0-15 used)

    // prologue: stages 0, 1
    #pragma unroll
    for (int p = 0; p < 2; p++) {
        uint32_t sa = su + p * STAGE_BYTES, sb = sa + 16384;
        const __half* ag = Ag + (size_t)lr * KTOT + p * BK + lc4 * 8;
        const __half* bg = Bg + (size_t)lr * KTOT + p * BK + lc4 * 8;
        #pragma unroll
        for (int j = 0; j < 4; j++) {
            int c = lc4 + j;
            uint32_t off = (uint32_t)(lr * 128 + ((c ^ (lr & 7)) * 16));
            cp16(sa + off, ag + j * 8);
            cp16(sb + off, bg + j * 8);
        }
        asm volatile("cp.async.commit_group;" ::: "memory");
    }

    for (int kt = 0; kt < NKT; kt++) {
        int s = kt % STAGES;
        if (kt == NKT - 1) asm volatile("cp.async.wait_group 0;" ::: "memory");
        else               asm volatile("cp.async.wait_group 1;" ::: "memory");
        __syncthreads();   // publish stage kt to all warps; also guards buffer reuse

        if (kt + 2 < NKT) {   // prefetch stage kt+2 into buffer (kt+2)%3
            int p = kt + 2;
            uint32_t sa = su + (p % STAGES) * STAGE_BYTES, sb = sa + 16384;
            const __half* ag = Ag + (size_t)lr * KTOT + p * BK + lc4 * 8;
            const __half* bg = Bg + (size_t)lr * KTOT + p * BK + lc4 * 8;
            #pragma unroll
            for (int j = 0; j < 4; j++) {
                int c = lc4 + j;
                uint32_t off = (uint32_t)(lr * 128 + ((c ^ (lr & 7)) * 16));
                cp16(sa + off, ag + j * 8);
                cp16(sb + off, bg + j * 8);
            }
            asm volatile("cp.async.commit_group;" ::: "memory");
        }

        uint32_t sa = su + s * STAGE_BYTES, sb = sa + 16384;
        #pragma unroll
        for (int ks = 0; ks < 4; ks++) {       // 4 k16 steps in BK=64
            uint32_t af[4][4], bf[4][2];
            #pragma unroll
            for (int mi = 0; mi < 4; mi++) {
                int r = mOff + mi * 16 + a_r;
                int c = ks * 2 + a_k;
                uint32_t ad = sa + (uint32_t)(r * 128 + ((c ^ (r & 7)) * 16));
                asm volatile(
                    "ldmatrix.sync.aligned.m8n8.x4.shared.b16 {%0,%1,%2,%3}, [%4];"
                    : "=r"(af[mi][0]), "=r"(af[mi][1]), "=r"(af[mi][2]), "=r"(af[mi][3])
                    : "r"(ad));
            }
            #pragma unroll
            for (int ni = 0; ni < 4; ni++) {
                int r = nOff + ni * 8 + b_r;
                int c = ks * 2 + b_k;
                uint32_t bd = sb + (uint32_t)(r * 128 + ((c ^ (r & 7)) * 16));
                asm volatile(
                    "ldmatrix.sync.aligned.m8n8.x2.shared.b16 {%0,%1}, [%2];"
                    : "=r"(bf[ni][0]), "=r"(bf[ni][1])
                    : "r"(bd));
            }
            #pragma unroll
            for (int mi = 0; mi < 4; mi++)
                #pragma unroll
                for (int ni = 0; ni < 4; ni++) {
                    asm volatile(
                        "mma.sync.aligned.m16n8k16.row.col.f32.f16.f16.f32 "
                        "{%0,%1,%2,%3}, {%4,%5,%6,%7}, {%8,%9}, {%0,%1,%2,%3};"
                        : "+f"(acc[mi][ni][0]), "+f"(acc[mi][ni][1]),
                          "+f"(acc[mi][ni][2]), "+f"(acc[mi][ni][3])
                        : "r"(af[mi][0]), "r"(af[mi][1]), "r"(af[mi][2]), "r"(af[mi][3]),
                          "r"(bf[ni][0]), "r"(bf[ni][1]));
                }
        }
    }

    // epilogue: C fragment layout -> float2 global stores
    int gid = lane >> 2, tig = lane & 3;
    #pragma unroll
    for (int mi = 0; mi < 4; mi++) {
        int r0 = rowBase + mOff + mi * 16 + gid;
        #pragma unroll
        for (int ni = 0; ni < 4; ni++) {
            int cc = colBase + nOff + ni * 8 + tig * 2;
            float2 v0 = make_float2(acc[mi][ni][0], acc[mi][ni][1]);
            float2 v1 = make_float2(acc[mi][ni][2], acc[mi][ni][3]);
            *(float2*)&out[(size_t)r0 * OUTSZ + cc]       = v0;
            *(float2*)&out[(size_t)(r0 + 8) * OUTSZ + cc] = v1;
        }
    }
}

// ----------------------------------------------------------------- launch
extern "C" void kernel_launch(void* const* d_in, const int* in_sizes, int n_in,
                              void* d_out, int out_size) {
    const float* x  = (const float*)d_in[0];   // (16384, 512)
    const float* bw = (const float*)d_in[1];   // (512, 512)
    const float* cw = (const float*)d_in[2];   // (512, 512, 10)
    float* out = (float*)d_out;

    cudaFuncSetAttribute(gemm_hmma_kernel,
                         cudaFuncAttributeMaxDynamicSharedMemorySize, SMEM_BYTES);

    build_wc_kernel<<<(OUTSZ * KTOT) / 256, 256>>>(bw, cw);
    build_act_kernel<<<BSZ, INSZ>>>(x);

    dim3 grid(OUTSZ / BN, BSZ / BM);   // (4, 128)
    gemm_hmma_kernel<<<grid, 256, SMEM_BYTES>>>(out);
}

// round 6
// speedup vs baseline: 4.7687x; 1.0003x over previous
#include <cuda_runtime.h>
#include <cuda_fp16.h>
#include <math.h>
#include <stdint.h>

// ---------------------------------------------------------------- constants
#define BSZ   16384
#define INSZ  512
#define OUTSZ 512
#define ORD   10
#define KTOT  5632              // 512 silu + 10*512 scrambled chebyshev
#define BM    128
#define BN    128
#define BK    64
#define NKT   (KTOT / BK)       // 88
#define STAGES 3
#define STAGE_BYTES 32768       // A 16KB + B 16KB
#define SMEM_BYTES  (STAGES * STAGE_BYTES)   // 98304

// ---------------------------------------------------------------- scratch
__device__ __align__(16) __half g_a[(size_t)BSZ * KTOT];   // 176 MB
__device__ __align__(16) __half g_b[(size_t)OUTSZ * KTOT]; // 5.6 MB

// --------------------------------------------------------------- builders
// Wc[out, 0:512] = base_weight ; Wc[out, 512+j] = 0.1 * cheby.flat[out*5120+j]
__global__ void build_wc_kernel(const float* __restrict__ base_w,
                                const float* __restrict__ cheby_w) {
    int idx = blockIdx.x * blockDim.x + threadIdx.x;  // 512*5632 threads
    int out = idx / KTOT;
    int k   = idx - out * KTOT;
    float v = (k < INSZ) ? base_w[out * INSZ + k]
                         : 0.1f * cheby_w[out * (INSZ * ORD) + (k - INSZ)];
    g_b[idx] = __float2half_rn(v);
}

// Act[b,i]=silu(x[b,i]); Act[b,512+o'*512+i]=T_o(x[bb,i]) with m=10b+o', o=m>>14,
// bb=m&16383. Iterate (o,bb): m=o*16384+bb, b=m/10, o'=m%10 (coalesced writes).
__global__ void build_act_kernel(const float* __restrict__ x) {
    int bb = blockIdx.x;
    int i  = threadIdx.x;
    float xv = x[bb * INSZ + i];

    float s = xv / (1.0f + expf(-xv));
    g_a[(size_t)bb * KTOT + i] = __float2half_rn(s);

    float tm2 = 1.0f, tm1 = xv;
    #pragma unroll
    for (int o = 0; o < ORD; o++) {
        float t;
        if (o == 0)      t = 1.0f;
        else if (o == 1) t = xv;
        else { t = 2.0f * xv * tm1 - tm2; tm2 = tm1; tm1 = t; }
        int m  = o * BSZ + bb;
        int b  = m / 10;
        int op = m - b * 10;
        g_a[(size_t)b * KTOT + INSZ + op * INSZ + i] = __float2half_rn(t);
    }
}

// --------------------------------------------------------- PTX primitives
__device__ __forceinline__ uint32_t smem_u32(const void* p) {
    uint32_t a;
    asm("{ .reg .u64 t; cvta.to.shared.u64 t, %1; cvt.u32.u64 %0, t; }" : "=r"(a) : "l"(p));
    return a;
}
__device__ __forceinline__ void cp16(uint32_t dst, const void* src) {
    asm volatile("cp.async.cg.shared.global [%0], [%1], 16;" :: "r"(dst), "l"(src));
}

// ------------------------------------------------------------- HMMA GEMM
// C[16384, 512] = A[16384, 5632] @ B[512, 5632]^T, fp16 in, fp32 accum.
// CTA 128x128, BK=64, 3-stage cp.async pipeline, 8 warps (2m x 4n),
// warp tile 64x32. Fragments double-buffered across the 4 k16 steps;
// B loaded via ldmatrix.x4 (two n8 tiles per load).
// SMEM tiles: [row][64 fp16] = 128B rows; 16B chunk c swizzled c^(row&7).
__global__ void __launch_bounds__(256, 2) gemm_hmma_kernel(float* __restrict__ out) {
    extern __shared__ char smem[];
    uint32_t su = smem_u32(smem);
    int tid = threadIdx.x, lane = tid & 31, wid = tid >> 5;
    int mOff = (wid & 1) * 64;
    int nOff = (wid >> 1) * 32;
    int rowBase = blockIdx.y * BM;
    int colBase = blockIdx.x * BN;

    const __half* Ag = g_a + (size_t)rowBase * KTOT;
    const __half* Bg = g_b + (size_t)colBase * KTOT;

    // loader: 128 rows x 8 chunks(16B); 2 threads/row, 4 chunks each
    int lr  = tid >> 1;          // 0..127
    int lc4 = (tid & 1) * 4;     // chunk base 0 or 4

    float acc[4][4][4];
    #pragma unroll
    for (int mi = 0; mi < 4; mi++)
        #pragma unroll
        for (int ni = 0; ni < 4; ni++)
            #pragma unroll
            for (int q = 0; q < 4; q++) acc[mi][ni][q] = 0.0f;

    // ldmatrix lane address components (x4: 16 rows, 2 k-chunks)
    int f_r = lane & 15, f_k = lane >> 4;

    // prologue: stages 0, 1
    #pragma unroll
    for (int p = 0; p < 2; p++) {
        uint32_t sa = su + p * STAGE_BYTES, sb = sa + 16384;
        const __half* ag = Ag + (size_t)lr * KTOT + p * BK + lc4 * 8;
        const __half* bg = Bg + (size_t)lr * KTOT + p * BK + lc4 * 8;
        #pragma unroll
        for (int j = 0; j < 4; j++) {
            int c = lc4 + j;
            uint32_t off = (uint32_t)(lr * 128 + ((c ^ (lr & 7)) * 16));
            cp16(sa + off, ag + j * 8);
            cp16(sb + off, bg + j * 8);
        }
        asm volatile("cp.async.commit_group;" ::: "memory");
    }

    uint32_t af[2][4][4];   // [buf][mi][4]
    uint32_t bf[2][2][4];   // [buf][npair][4]  (r0,r2)->ni even  (r1,r3)->ni odd

    for (int kt = 0; kt < NKT; kt++) {
        int s = kt % STAGES;
        if (kt == NKT - 1) asm volatile("cp.async.wait_group 0;" ::: "memory");
        else               asm volatile("cp.async.wait_group 1;" ::: "memory");
        __syncthreads();   // publish stage kt; also guards buffer reuse

        uint32_t sa = su + s * STAGE_BYTES, sb = sa + 16384;

        // load fragments for ks=0 into buf 0
        {
            int c = f_k;   // ks=0
            #pragma unroll
            for (int mi = 0; mi < 4; mi++) {
                int r = mOff + mi * 16 + f_r;
                uint32_t ad = sa + (uint32_t)(r * 128 + ((c ^ (r & 7)) * 16));
                asm volatile(
                    "ldmatrix.sync.aligned.m8n8.x4.shared.b16 {%0,%1,%2,%3}, [%4];"
                    : "=r"(af[0][mi][0]), "=r"(af[0][mi][1]),
                      "=r"(af[0][mi][2]), "=r"(af[0][mi][3]) : "r"(ad));
            }
            #pragma unroll
            for (int p = 0; p < 2; p++) {
                int r = nOff + p * 16 + f_r;
                uint32_t bd = sb + (uint32_t)(r * 128 + ((c ^ (r & 7)) * 16));
                asm volatile(
                    "ldmatrix.sync.aligned.m8n8.x4.shared.b16 {%0,%1,%2,%3}, [%4];"
                    : "=r"(bf[0][p][0]), "=r"(bf[0][p][1]),
                      "=r"(bf[0][p][2]), "=r"(bf[0][p][3]) : "r"(bd));
            }
        }

        // global prefetch for stage kt+2 (issues overlap ks=0 LDSM latency)
        if (kt + 2 < NKT) {
            int p = kt + 2;
            uint32_t pa = su + (p % STAGES) * STAGE_BYTES, pb = pa + 16384;
            const __half* ag = Ag + (size_t)lr * KTOT + p * BK + lc4 * 8;
            const __half* bg = Bg + (size_t)lr * KTOT + p * BK + lc4 * 8;
            #pragma unroll
            for (int j = 0; j < 4; j++) {
                int c = lc4 + j;
                uint32_t off = (uint32_t)(lr * 128 + ((c ^ (lr & 7)) * 16));
                cp16(pa + off, ag + j * 8);
                cp16(pb + off, bg + j * 8);
            }
            asm volatile("cp.async.commit_group;" ::: "memory");
        }

        #pragma unroll
        for (int ks = 0; ks < 4; ks++) {
            int cu = ks & 1;
            if (ks < 3) {                      // prefetch ks+1 fragments
                int c = (ks + 1) * 2 + f_k;
                #pragma unroll
                for (int mi = 0; mi < 4; mi++) {
                    int r = mOff + mi * 16 + f_r;
                    uint32_t ad = sa + (uint32_t)(r * 128 + ((c ^ (r & 7)) * 16));
                    asm volatile(
                        "ldmatrix.sync.aligned.m8n8.x4.shared.b16 {%0,%1,%2,%3}, [%4];"
                        : "=r"(af[cu ^ 1][mi][0]), "=r"(af[cu ^ 1][mi][1]),
                          "=r"(af[cu ^ 1][mi][2]), "=r"(af[cu ^ 1][mi][3]) : "r"(ad));
                }
                #pragma unroll
                for (int p = 0; p < 2; p++) {
                    int r = nOff + p * 16 + f_r;
                    uint32_t bd = sb + (uint32_t)(r * 128 + ((c ^ (r & 7)) * 16));
                    asm volatile(
                        "ldmatrix.sync.aligned.m8n8.x4.shared.b16 {%0,%1,%2,%3}, [%4];"
                        : "=r"(bf[cu ^ 1][p][0]), "=r"(bf[cu ^ 1][p][1]),
                          "=r"(bf[cu ^ 1][p][2]), "=r"(bf[cu ^ 1][p][3]) : "r"(bd));
                }
            }
            #pragma unroll
            for (int mi = 0; mi < 4; mi++)
                #pragma unroll
                for (int p = 0; p < 2; p++) {
                    asm volatile(
                        "mma.sync.aligned.m16n8k16.row.col.f32.f16.f16.f32 "
                        "{%0,%1,%2,%3}, {%4,%5,%6,%7}, {%8,%9}, {%0,%1,%2,%3};"
                        : "+f"(acc[mi][2 * p][0]), "+f"(acc[mi][2 * p][1]),
                          "+f"(acc[mi][2 * p][2]), "+f"(acc[mi][2 * p][3])
                        : "r"(af[cu][mi][0]), "r"(af[cu][mi][1]),
                          "r"(af[cu][mi][2]), "r"(af[cu][mi][3]),
                          "r"(bf[cu][p][0]), "r"(bf[cu][p][2]));
                    asm volatile(
                        "mma.sync.aligned.m16n8k16.row.col.f32.f16.f16.f32 "
                        "{%0,%1,%2,%3}, {%4,%5,%6,%7}, {%8,%9}, {%0,%1,%2,%3};"
                        : "+f"(acc[mi][2 * p + 1][0]), "+f"(acc[mi][2 * p + 1][1]),
                          "+f"(acc[mi][2 * p + 1][2]), "+f"(acc[mi][2 * p + 1][3])
                        : "r"(af[cu][mi][0]), "r"(af[cu][mi][1]),
                          "r"(af[cu][mi][2]), "r"(af[cu][mi][3]),
                          "r"(bf[cu][p][1]), "r"(bf[cu][p][3]));
                }
        }
    }

    // epilogue: C fragment layout -> float2 global stores
    int gid = lane >> 2, tig = lane & 3;
    #pragma unroll
    for (int mi = 0; mi < 4; mi++) {
        int r0 = rowBase + mOff + mi * 16 + gid;
        #pragma unroll
        for (int ni = 0; ni < 4; ni++) {
            int cc = colBase + nOff + ni * 8 + tig * 2;
            float2 v0 = make_float2(acc[mi][ni][0], acc[mi][ni][1]);
            float2 v1 = make_float2(acc[mi][ni][2], acc[mi][ni][3]);
            *(float2*)&out[(size_t)r0 * OUTSZ + cc]       = v0;
            *(float2*)&out[(size_t)(r0 + 8) * OUTSZ + cc] = v1;
        }
    }
}

// ----------------------------------------------------------------- launch
extern "C" void kernel_launch(void* const* d_in, const int* in_sizes, int n_in,
                              void* d_out, int out_size) {
    const float* x  = (const float*)d_in[0];   // (16384, 512)
    const float* bw = (const float*)d_in[1];   // (512, 512)
    const float* cw = (const float*)d_in[2];   // (512, 512, 10)
    float* out = (float*)d_out;

    cudaFuncSetAttribute(gemm_hmma_kernel,
                         cudaFuncAttributeMaxDynamicSharedMemorySize, SMEM_BYTES);

    build_wc_kernel<<<(OUTSZ * KTOT) / 256, 256>>>(bw, cw);
    build_act_kernel<<<BSZ, INSZ>>>(x);

    dim3 grid(OUTSZ / BN, BSZ / BM);   // (4, 128)
    gemm_hmma_kernel<<<grid, 256, SMEM_BYTES>>>(out);
}

// round 7
// speedup vs baseline: 4.9933x; 1.0471x over previous
#include <cuda_runtime.h>
#include <cuda_fp16.h>
#include <math.h>
#include <stdint.h>

// ---------------------------------------------------------------- constants
#define BSZ   16384
#define INSZ  512
#define OUTSZ 512
#define ORD   10
#define KTOT  5632              // 512 silu + 10*512 scrambled chebyshev
#define BM    128
#define BN    128
#define BK    64
#define NKT   (KTOT / BK)       // 88
#define STAGES 3
#define STAGE_BYTES 32768       // A 16KB + B 16KB
#define SMEM_BYTES  (STAGES * STAGE_BYTES)   // 98304

// ---------------------------------------------------------------- scratch
__device__ __align__(16) __half g_a[(size_t)BSZ * KTOT];   // 176 MB
__device__ __align__(16) __half g_b[(size_t)OUTSZ * KTOT]; // 5.6 MB

// --------------------------------------------------------- merged builder
// blocks [0, BSZ):           Act rows (scrambled chebyshev + silu)
// blocks [BSZ, BSZ+5632):    Wc, 512 elements per block
__global__ void build_all_kernel(const float* __restrict__ x,
                                 const float* __restrict__ base_w,
                                 const float* __restrict__ cheby_w) {
    int blk = blockIdx.x;
    int i   = threadIdx.x;                     // 0..511
    if (blk < BSZ) {
        int bb = blk;
        float xv = x[bb * INSZ + i];
        float s = xv / (1.0f + expf(-xv));
        g_a[(size_t)bb * KTOT + i] = __float2half_rn(s);

        float tm2 = 1.0f, tm1 = xv;
        #pragma unroll
        for (int o = 0; o < ORD; o++) {
            float t;
            if (o == 0)      t = 1.0f;
            else if (o == 1) t = xv;
            else { t = 2.0f * xv * tm1 - tm2; tm2 = tm1; tm1 = t; }
            int m  = o * BSZ + bb;
            int b  = m / 10;
            int op = m - b * 10;
            g_a[(size_t)b * KTOT + INSZ + op * INSZ + i] = __float2half_rn(t);
        }
    } else {
        int idx = (blk - BSZ) * 512 + i;       // 0 .. 512*5632-1
        int out = idx / KTOT;
        int k   = idx - out * KTOT;
        float v = (k < INSZ) ? base_w[out * INSZ + k]
                             : 0.1f * cheby_w[out * (INSZ * ORD) + (k - INSZ)];
        g_b[idx] = __float2half_rn(v);
    }
}

// --------------------------------------------------------- PTX primitives
__device__ __forceinline__ uint32_t smem_u32(const void* p) {
    uint32_t a;
    asm("{ .reg .u64 t; cvta.to.shared.u64 t, %1; cvt.u32.u64 %0, t; }" : "=r"(a) : "l"(p));
    return a;
}
__device__ __forceinline__ void cp16(uint32_t dst, const void* src) {
    asm volatile("cp.async.cg.shared.global [%0], [%1], 16;" :: "r"(dst), "l"(src));
}
#define LDSM_X4(d0, d1, d2, d3, addr)                                          \
    asm volatile("ldmatrix.sync.aligned.m8n8.x4.shared.b16 {%0,%1,%2,%3}, [%4];" \
                 : "=r"(d0), "=r"(d1), "=r"(d2), "=r"(d3) : "r"(addr))
#define HMMA(acc, a, b0, b1)                                                   \
    asm volatile("mma.sync.aligned.m16n8k16.row.col.f32.f16.f16.f32 "          \
                 "{%0,%1,%2,%3}, {%4,%5,%6,%7}, {%8,%9}, {%0,%1,%2,%3};"       \
                 : "+f"(acc[0]), "+f"(acc[1]), "+f"(acc[2]), "+f"(acc[3])      \
                 : "r"(a[0]), "r"(a[1]), "r"(a[2]), "r"(a[3]), "r"(b0), "r"(b1))

// ------------------------------------------------------------- HMMA GEMM
// C[16384,512] = A[16384,5632] @ B[512,5632]^T, fp16 in, fp32 accum.
// CTA 128x128, BK=64, 3-stage cp.async pipeline, 8 warps (2m x 4n),
// warp tile 64x32. Chunk-level software pipeline: the {wait, sync, next-chunk
// ks0 fragment loads, global prefetch} transition sits between ks=2 and ks=3,
// so the trailing 16 HMMAs hide barrier skew + LDSM latency.
__global__ void __launch_bounds__(256, 2) gemm_hmma_kernel(float* __restrict__ out) {
    extern __shared__ char smem[];
    uint32_t su = smem_u32(smem);
    int tid = threadIdx.x, lane = tid & 31, wid = tid >> 5;
    int mOff = (wid & 1) * 64;
    int nOff = (wid >> 1) * 32;
    int rowBase = blockIdx.y * BM;
    int colBase = blockIdx.x * BN;

    const __half* Ag = g_a + (size_t)rowBase * KTOT;
    const __half* Bg = g_b + (size_t)colBase * KTOT;

    // loader mapping: 128 rows x 8 chunks(16B); 2 threads/row, 4 chunks each
    int lr  = tid >> 1;
    int lc4 = (tid & 1) * 4;
    const __half* agb = Ag + (size_t)lr * KTOT + lc4 * 8;
    const __half* bgb = Bg + (size_t)lr * KTOT + lc4 * 8;

    float acc[4][4][4];
    #pragma unroll
    for (int mi = 0; mi < 4; mi++)
        #pragma unroll
        for (int ni = 0; ni < 4; ni++)
            #pragma unroll
            for (int q = 0; q < 4; q++) acc[mi][ni][q] = 0.0f;

    int f_r = lane & 15, f_k = lane >> 4;   // ldmatrix x4 lane mapping

    uint32_t af[2][4][4];   // [buf][mi][4]
    uint32_t bf[2][2][4];   // [buf][npair][4]; regs {0,2}->ni even, {1,3}->ni odd

    // issue global loads for chunks 0, 1
    #pragma unroll
    for (int p = 0; p < 2; p++) {
        uint32_t sa = su + p * STAGE_BYTES, sb = sa + 16384;
        #pragma unroll
        for (int j = 0; j < 4; j++) {
            int c = lc4 + j;
            uint32_t off = (uint32_t)(lr * 128 + ((c ^ (lr & 7)) * 16));
            cp16(sa + off, agb + p * BK + j * 8);
            cp16(sb + off, bgb + p * BK + j * 8);
        }
        asm volatile("cp.async.commit_group;" ::: "memory");
    }

    // fragment loader for (stage, ks) into buffer bu
    auto load_frags = [&](uint32_t sa, uint32_t sb, int ks, int bu) {
        int c = ks * 2 + f_k;
        #pragma unroll
        for (int mi = 0; mi < 4; mi++) {
            int r = mOff + mi * 16 + f_r;
            uint32_t ad = sa + (uint32_t)(r * 128 + ((c ^ (r & 7)) * 16));
            LDSM_X4(af[bu][mi][0], af[bu][mi][1], af[bu][mi][2], af[bu][mi][3], ad);
        }
        #pragma unroll
        for (int p = 0; p < 2; p++) {
            int r = nOff + p * 16 + f_r;
            uint32_t bd = sb + (uint32_t)(r * 128 + ((c ^ (r & 7)) * 16));
            LDSM_X4(bf[bu][p][0], bf[bu][p][1], bf[bu][p][2], bf[bu][p][3], bd);
        }
    };
    auto mma_step = [&](int bu) {
        #pragma unroll
        for (int mi = 0; mi < 4; mi++)
            #pragma unroll
            for (int p = 0; p < 2; p++) {
                HMMA(acc[mi][2 * p],     af[bu][mi], bf[bu][p][0], bf[bu][p][2]);
                HMMA(acc[mi][2 * p + 1], af[bu][mi], bf[bu][p][1], bf[bu][p][3]);
            }
    };

    // prologue: drain chunk 0 (group 1 may pend), publish, load its ks0 frags
    asm volatile("cp.async.wait_group 1;" ::: "memory");
    __syncthreads();
    load_frags(su, su + 16384, 0, 0);

    for (int kt = 0; kt < NKT; kt++) {
        uint32_t sa = su + (kt % STAGES) * STAGE_BYTES, sb = sa + 16384;

        #pragma unroll
        for (int ks = 0; ks < 3; ks++) {
            load_frags(sa, sb, ks + 1, (ks & 1) ^ 1);   // prefetch ks+1
            mma_step(ks & 1);                            // MMA ks
        }

        // ---- transition (before the trailing ks=3 MMAs) ----
        if (kt + 1 < NKT) {
            // pending = {kt+1} exactly -> drain it, publish its stage
            asm volatile("cp.async.wait_group 0;" ::: "memory");
            __syncthreads();
            uint32_t na = su + ((kt + 1) % STAGES) * STAGE_BYTES, nb = na + 16384;
            load_frags(na, nb, 0, 0);                    // next chunk ks0 -> buf 0
            if (kt + 2 < NKT) {                          // issue chunk kt+2
                uint32_t pa = su + ((kt + 2) % STAGES) * STAGE_BYTES, pb = pa + 16384;
                #pragma unroll
                for (int j = 0; j < 4; j++) {
                    int c = lc4 + j;
                    uint32_t off = (uint32_t)(lr * 128 + ((c ^ (lr & 7)) * 16));
                    cp16(pa + off, agb + (size_t)(kt + 2) * BK + j * 8);
                    cp16(pb + off, bgb + (size_t)(kt + 2) * BK + j * 8);
                }
                asm volatile("cp.async.commit_group;" ::: "memory");
            }
        }

        mma_step(1);                                     // MMA ks=3 (buf 1)
    }

    // epilogue: C fragment layout -> float2 global stores
    int gid = lane >> 2, tig = lane & 3;
    #pragma unroll
    for (int mi = 0; mi < 4; mi++) {
        int r0 = rowBase + mOff + mi * 16 + gid;
        #pragma unroll
        for (int ni = 0; ni < 4; ni++) {
            int cc = colBase + nOff + ni * 8 + tig * 2;
            float2 v0 = make_float2(acc[mi][ni][0], acc[mi][ni][1]);
            float2 v1 = make_float2(acc[mi][ni][2], acc[mi][ni][3]);
            *(float2*)&out[(size_t)r0 * OUTSZ + cc]       = v0;
            *(float2*)&out[(size_t)(r0 + 8) * OUTSZ + cc] = v1;
        }
    }
}

// ----------------------------------------------------------------- launch
extern "C" void kernel_launch(void* const* d_in, const int* in_sizes, int n_in,
                              void* d_out, int out_size) {
    const float* x  = (const float*)d_in[0];   // (16384, 512)
    const float* bw = (const float*)d_in[1];   // (512, 512)
    const float* cw = (const float*)d_in[2];   // (512, 512, 10)
    float* out = (float*)d_out;

    cudaFuncSetAttribute(gemm_hmma_kernel,
                         cudaFuncAttributeMaxDynamicSharedMemorySize, SMEM_BYTES);

    build_all_kernel<<<BSZ + (OUTSZ * KTOT) / 512, 512>>>(x, bw, cw);

    dim3 grid(OUTSZ / BN, BSZ / BM);   // (4, 128)
    gemm_hmma_kernel<<<grid, 256, SMEM_BYTES>>>(out);
}